// round 15
// baseline (speedup 1.0000x reference)
#include <cuda_runtime.h>
#include <cuda_bf16.h>
#include <math.h>
#include <stdint.h>

typedef __nv_bfloat16 bf16;

#define Sn   2048
#define HIDn 2048
#define NHn  16
#define HDn  128
#define DCn  256

#define BMh  128
#define BNh  128
#define BKh  32
#define NTHR 256
#define ROWB 64
#define TILE_B (BMh * ROWB)            // 8KB per operand tile
#define STAGE_B (4 * TILE_B)           // Ah, Al, Bh, Bl = 32KB per stage
#define NSTAGE 3
#define SMEM_DYN (NSTAGE * STAGE_B)    // 96KB

// ---------------- device globals (scratch) ----------------
static __device__ __align__(1024) bf16 g_Xmu_h[Sn*HIDn], g_Xmu_l[Sn*HIDn];
static __device__ __align__(1024) bf16 g_Xls_h[Sn*HIDn], g_Xls_l[Sn*HIDn];
static __device__ __align__(1024) bf16 g_W_h[8][HIDn*HIDn];
static __device__ __align__(1024) bf16 g_W_l[8][HIDn*HIDn];
static __device__ __align__(1024) float g_proj[6][(size_t)Sn*HIDn];
static __device__ __align__(1024) bf16 g_Q_h[(size_t)NHn*Sn*DCn], g_Q_l[(size_t)NHn*Sn*DCn];
static __device__ __align__(1024) bf16 g_K_h[(size_t)NHn*Sn*DCn], g_K_l[(size_t)NHn*Sn*DCn];
static __device__ __align__(1024) bf16 g_Vt_h[(size_t)NHn*DCn*Sn], g_Vt_l[(size_t)NHn*DCn*Sn];
static __device__ __align__(1024) float g_P[(size_t)NHn*Sn*Sn];
static __device__ __align__(1024) bf16 g_P_h[(size_t)NHn*Sn*Sn], g_P_l[(size_t)NHn*Sn*Sn];
static __device__ __align__(1024) bf16 g_Om_h[Sn*HIDn], g_Om_l[Sn*HIDn];
static __device__ __align__(1024) bf16 g_Ol_h[Sn*HIDn], g_Ol_l[Sn*HIDn];
static __device__ float g_kn[NHn*Sn];

// ---------------- helpers ----------------
__device__ __forceinline__ uint32_t smem_u32(const void* p){
    uint32_t a;
    asm("{ .reg .u64 t; cvta.to.shared.u64 t, %1; cvt.u32.u64 %0, t; }" : "=r"(a) : "l"(p));
    return a;
}
__device__ __forceinline__ void cp16(uint32_t dst, const void* src){
    asm volatile("cp.async.cg.shared.global [%0], [%1], 16;" :: "r"(dst), "l"(src) : "memory");
}
#define CP_COMMIT() asm volatile("cp.async.commit_group;" ::: "memory")
#define CP_WAIT1()  asm volatile("cp.async.wait_group 1;" ::: "memory")

__device__ __forceinline__ void ldsm4(uint32_t* r, uint32_t addr){
    asm volatile("ldmatrix.sync.aligned.m8n8.x4.shared.b16 {%0,%1,%2,%3}, [%4];"
                 : "=r"(r[0]), "=r"(r[1]), "=r"(r[2]), "=r"(r[3]) : "r"(addr));
}
__device__ __forceinline__ void hmma(float* d, const uint32_t* a, uint32_t b0, uint32_t b1){
    asm volatile("mma.sync.aligned.m16n8k16.row.col.f32.bf16.bf16.f32 "
                 "{%0,%1,%2,%3}, {%4,%5,%6,%7}, {%8,%9}, {%0,%1,%2,%3};"
                 : "+f"(d[0]), "+f"(d[1]), "+f"(d[2]), "+f"(d[3])
                 : "r"(a[0]), "r"(a[1]), "r"(a[2]), "r"(a[3]), "r"(b0), "r"(b1));
}
__device__ __forceinline__ uint32_t sw_off(int row, int chunk){
    return (uint32_t)(row * ROWB + ((chunk ^ ((row >> 1) & 3)) << 4));
}
__device__ __forceinline__ uint32_t pack_hi(float a, float b, uint32_t& lo){
    bf16 h0 = __float2bfloat16(a), h1 = __float2bfloat16(b);
    __nv_bfloat162 hh; hh.x = h0; hh.y = h1;
    __nv_bfloat162 ll;
    ll.x = __float2bfloat16(a - __bfloat162float(h0));
    ll.y = __float2bfloat16(b - __bfloat162float(h1));
    lo = *(uint32_t*)&ll;
    return *(uint32_t*)&hh;
}

// ---------------- 4-tile stage loader ----------------
__device__ __forceinline__ void load_stage4(uint32_t st,
    const bf16* __restrict__ Ah, const bf16* __restrict__ Al,
    const bf16* __restrict__ Bh, const bf16* __restrict__ Bl,
    int lda, int ldb, int koff, int tid)
{
#pragma unroll
    for (int i = 0; i < 8; i++){
        const int tile = i >> 1;
        const int id = tid + i*NTHR;
        const int r = (id >> 2) & 127;
        const int c = id & 3;
        const bf16* base = (tile==0) ? Ah : (tile==1) ? Al : (tile==2) ? Bh : Bl;
        const int ld = (tile < 2) ? lda : ldb;
        cp16(st + tile*TILE_B + sw_off(r, c), base + (size_t)r*ld + koff + c*8);
    }
    CP_COMMIT();
}

enum { E_LOGIT = 1, E_SPLITPV = 2, E_PROJ6 = 3, E_OUT2 = 4 };

// ---------------- HMMA GEMM: C[M,N] = (Ah+Al)(Bh+Bl)^T via bf16x3 ----------------
// (R10 mainloop schedule — frozen. Only addition: per-CTA K-phase stagger to
//  decorrelate the two co-resident CTAs' barrier phases; accumulation order only.)
template<int MODE>
__global__ void __launch_bounds__(NTHR, 2)
hm_gemm(const bf16* __restrict__ Ah, const bf16* __restrict__ Al,
        const bf16* __restrict__ A2h, const bf16* __restrict__ A2l,
        const bf16* __restrict__ WhB, const bf16* __restrict__ WlB,
        float* __restrict__ C,
        bf16* __restrict__ OH, bf16* __restrict__ OL,
        bf16* __restrict__ OH2, bf16* __restrict__ OL2,
        int K, int lda, int ldb, int ldc,
        long long sA, long long sB, long long sC,
        const float* __restrict__ knArr, const float* __restrict__ tau)
{
    extern __shared__ __align__(128) char smem[];
    const uint32_t sb = smem_u32(smem);
    const int tid  = threadIdx.x;
    const int lane = tid & 31;
    const int wid  = tid >> 5;
    const int wm = wid & 3;
    const int wn = wid >> 2;
    const int z = blockIdx.z;
    const int mbase = blockIdx.y * BMh, nbase = blockIdx.x * BNh;

    const bf16 *bAh, *bAl, *bBh, *bBl;
    float* Cz = C;
    if (MODE == E_PROJ6){
        const bool ls = (z >= 3);
        bAh = ls ? A2h : Ah;  bAl = ls ? A2l : Al;
        const int wsel = ls ? (z + 1) : z;
        bBh = WhB + (size_t)wsel*HIDn*HIDn;
        bBl = WlB + (size_t)wsel*HIDn*HIDn;
        Cz = C + (size_t)z*Sn*HIDn;
    } else if (MODE == E_OUT2){
        bAh = z ? A2h : Ah;  bAl = z ? A2l : Al;
        const int wsel = z ? 7 : 3;
        bBh = WhB + (size_t)wsel*HIDn*HIDn;
        bBl = WlB + (size_t)wsel*HIDn*HIDn;
        Cz = C + (size_t)z*Sn*HIDn;
    } else {
        bAh = Ah + (size_t)z*sA;  bAl = Al + (size_t)z*sA;
        bBh = WhB + (size_t)z*sB; bBl = WlB + (size_t)z*sB;
        Cz = C + (size_t)z*sC;
    }
    const bf16* pAh = bAh + (size_t)mbase*lda;
    const bf16* pAl = bAl + (size_t)mbase*lda;
    const bf16* pBh = bBh + (size_t)nbase*ldb;
    const bf16* pBl = bBl + (size_t)nbase*ldb;

    const int kbn = K / BKh;
    // K-phase stagger: odd-parity CTAs start halfway through the K range.
    const int kphase = ((blockIdx.x + blockIdx.y + blockIdx.z) & 1) ? (kbn >> 1) : 0;

    float acc[2][8][4];
#pragma unroll
    for (int i = 0; i < 2; i++)
#pragma unroll
        for (int j = 0; j < 8; j++)
#pragma unroll
            for (int q = 0; q < 4; q++) acc[i][j][q] = 0.f;

    const int aRow = wm*32 + (lane & 7) + 8*((lane >> 3) & 1);
    const int aChk = lane >> 4;
    const int bRow = wn*64 + (lane & 7) + 8*(lane >> 4);
    const int bChk = (lane >> 3) & 1;

    {
        int k0 = kphase;                          // kb = 0
        int k1 = kphase + 1; if (k1 >= kbn) k1 -= kbn;  // kb = 1
        load_stage4(sb + 0*STAGE_B, pAh, pAl, pBh, pBl, lda, ldb, k0*BKh, tid);
        load_stage4(sb + 1*STAGE_B, pAh, pAl, pBh, pBl, lda, ldb, k1*BKh, tid);
    }

    int stidx = 0;
    for (int kb = 0; kb < kbn; kb++){
        const uint32_t aTh = sb + stidx*STAGE_B;
        const uint32_t aTl = aTh + TILE_B;
        const uint32_t bTh = aTh + 2*TILE_B;
        const uint32_t bTl = aTh + 3*TILE_B;
        CP_WAIT1();
        __syncthreads();

#pragma unroll
        for (int s = 0; s < 2; s++){
            uint32_t ah[2][4], al[2][4], bh[4][4], bl[4][4];
#pragma unroll
            for (int mt = 0; mt < 2; mt++)
                ldsm4(ah[mt], aTh + sw_off(aRow + mt*16, 2*s + aChk));
#pragma unroll
            for (int np = 0; np < 4; np++)
                ldsm4(bh[np], bTh + sw_off(bRow + np*16, 2*s + bChk));
#pragma unroll
            for (int mt = 0; mt < 2; mt++)
#pragma unroll
                for (int nt = 0; nt < 8; nt++){
                    const uint32_t* bb = bh[nt >> 1];
                    const int o = (nt & 1) * 2;
                    hmma(acc[mt][nt], ah[mt], bb[o], bb[o+1]);
                }
#pragma unroll
            for (int mt = 0; mt < 2; mt++)
                ldsm4(al[mt], aTl + sw_off(aRow + mt*16, 2*s + aChk));
#pragma unroll
            for (int mt = 0; mt < 2; mt++)
#pragma unroll
                for (int nt = 0; nt < 8; nt++){
                    const uint32_t* bb = bh[nt >> 1];
                    const int o = (nt & 1) * 2;
                    hmma(acc[mt][nt], al[mt], bb[o], bb[o+1]);
                }
#pragma unroll
            for (int np = 0; np < 4; np++)
                ldsm4(bl[np], bTl + sw_off(bRow + np*16, 2*s + bChk));
#pragma unroll
            for (int mt = 0; mt < 2; mt++)
#pragma unroll
                for (int nt = 0; nt < 8; nt++){
                    const uint32_t* bb = bl[nt >> 1];
                    const int o = (nt & 1) * 2;
                    hmma(acc[mt][nt], ah[mt], bb[o], bb[o+1]);
                }
        }
        if (kb + 2 < kbn){
            const int nidx = (stidx + 2 >= NSTAGE) ? stidx + 2 - NSTAGE : stidx + 2;
            int kk = kb + 2 + kphase; if (kk >= kbn) kk -= kbn;
            load_stage4(sb + nidx*STAGE_B, pAh, pAl, pBh, pBl, lda, ldb, kk*BKh, tid);
        }
        stidx = (stidx + 1 == NSTAGE) ? 0 : stidx + 1;
    }

    // epilogue
    float invden = 1.0f;
    const float* knz = nullptr;
    if (MODE == E_LOGIT){
        invden = 1.0f / (fabsf(tau[0]) + 1e-6f);
        knz = knArr + (size_t)z * Sn;
    }
    const int rr = lane >> 2;
    const int cc = (lane & 3) * 2;
#pragma unroll
    for (int mt = 0; mt < 2; mt++){
#pragma unroll
        for (int nt = 0; nt < 8; nt++){
#pragma unroll
            for (int half = 0; half < 2; half++){
                int grow = mbase + wm*32 + mt*16 + rr + half*8;
                int gcol = nbase + wn*64 + nt*8 + cc;
                float v0 = acc[mt][nt][half*2 + 0];
                float v1 = acc[mt][nt][half*2 + 1];
                if (MODE == E_LOGIT){
                    v0 = (2.0f*v0 - knz[gcol])   * invden;
                    v1 = (2.0f*v1 - knz[gcol+1]) * invden;
                }
                if (MODE == E_SPLITPV){
                    bf16* dh = (nbase < HDn) ? OH : OH2;
                    bf16* dl = (nbase < HDn) ? OL : OL2;
                    size_t off = (size_t)grow*HIDn + (size_t)z*HDn + (gcol & (HDn-1));
                    uint32_t lo, hi = pack_hi(v0, v1, lo);
                    *(uint32_t*)(dh + off) = hi;
                    *(uint32_t*)(dl + off) = lo;
                } else {
                    float2 vv = make_float2(v0, v1);
                    float* dst = Cz + (size_t)grow*ldc + gcol;
                    *(float2*)dst = vv;
                }
            }
        }
    }
}

// ---------------- merged split: 10 matrices (8 W + xmu + xls), 8 elems/thread ---
__global__ void split10_v4(const float* __restrict__ w0, const float* __restrict__ w1,
                           const float* __restrict__ w2, const float* __restrict__ w3,
                           const float* __restrict__ w4, const float* __restrict__ w5,
                           const float* __restrict__ w6, const float* __restrict__ w7,
                           const float* __restrict__ xmu, const float* __restrict__ xls,
                           bf16* __restrict__ Wh, bf16* __restrict__ Wl,
                           bf16* __restrict__ Xmuh, bf16* __restrict__ Xmul,
                           bf16* __restrict__ Xlsh, bf16* __restrict__ Xlsl)
{
    const int w = blockIdx.y;
    const float* src;
    bf16 *dh, *dl;
    switch (w){
        case 0: src = w0;  dh = Wh + 0*(size_t)HIDn*HIDn; dl = Wl + 0*(size_t)HIDn*HIDn; break;
        case 1: src = w1;  dh = Wh + 1*(size_t)HIDn*HIDn; dl = Wl + 1*(size_t)HIDn*HIDn; break;
        case 2: src = w2;  dh = Wh + 2*(size_t)HIDn*HIDn; dl = Wl + 2*(size_t)HIDn*HIDn; break;
        case 3: src = w3;  dh = Wh + 3*(size_t)HIDn*HIDn; dl = Wl + 3*(size_t)HIDn*HIDn; break;
        case 4: src = w4;  dh = Wh + 4*(size_t)HIDn*HIDn; dl = Wl + 4*(size_t)HIDn*HIDn; break;
        case 5: src = w5;  dh = Wh + 5*(size_t)HIDn*HIDn; dl = Wl + 5*(size_t)HIDn*HIDn; break;
        case 6: src = w6;  dh = Wh + 6*(size_t)HIDn*HIDn; dl = Wl + 6*(size_t)HIDn*HIDn; break;
        case 7: src = w7;  dh = Wh + 7*(size_t)HIDn*HIDn; dl = Wl + 7*(size_t)HIDn*HIDn; break;
        case 8: src = xmu; dh = Xmuh; dl = Xmul; break;
        default: src = xls; dh = Xlsh; dl = Xlsl; break;
    }
    size_t i = (size_t)blockIdx.x*blockDim.x + threadIdx.x;
    const float4* in = (const float4*)src;
    float4 a = in[2*i], b = in[2*i + 1];
    float va[8] = {a.x, a.y, a.z, a.w, b.x, b.y, b.z, b.w};
    uint32_t hw[4], lw[4];
#pragma unroll
    for (int p = 0; p < 4; p++)
        hw[p] = pack_hi(va[2*p], va[2*p+1], lw[p]);
    ((uint4*)dh)[i] = make_uint4(hw[0], hw[1], hw[2], hw[3]);
    ((uint4*)dl)[i] = make_uint4(lw[0], lw[1], lw[2], lw[3]);
}

// ---------------- merged Q/K transform: rope + exp + split + kn(K only) ---------
__global__ void qk_transform2(const float* __restrict__ projBase,
                              const float* __restrict__ cosp, const float* __restrict__ sinp,
                              bf16* __restrict__ Qh, bf16* __restrict__ Ql,
                              bf16* __restrict__ Kh, bf16* __restrict__ Kl,
                              float* __restrict__ kn)
{
    const int which = blockIdx.z;
    const float* mu = projBase + (size_t)which     *Sn*HIDn;
    const float* ls = projBase + (size_t)(which+3) *Sn*HIDn;
    bf16* oh = which ? Kh : Qh;
    bf16* ol = which ? Kl : Ql;
    int s = blockIdx.x, h = blockIdx.y, d = threadIdx.x;
    size_t ib = (size_t)s*HIDn + h*HDn;
    float m = mu[ib + d];
    float o = mu[ib + ((d < 64) ? d + 64 : d - 64)];
    float c = cosp[s*HDn + d], sv = sinp[s*HDn + d];
    float roped = (d < 64) ? (m*c - o*sv) : (m*c + o*sv);
    float sg = expf(0.5f * ls[ib + d]);
    size_t ob = ((size_t)h*Sn + s)*DCn;
    bf16 hh = __float2bfloat16(roped);
    oh[ob + d] = hh; ol[ob + d] = __float2bfloat16(roped - __bfloat162float(hh));
    bf16 hs = __float2bfloat16(sg);
    oh[ob + 128 + d] = hs; ol[ob + 128 + d] = __float2bfloat16(sg - __bfloat162float(hs));
    if (which == 1){
        float acc = roped*roped + sg*sg;
#pragma unroll
        for (int off = 16; off; off >>= 1) acc += __shfl_xor_sync(0xffffffffu, acc, off);
        __shared__ float red[4];
        if ((d & 31) == 0) red[d>>5] = acc;
        __syncthreads();
        if (d == 0) kn[(size_t)h*Sn + s] = red[0] + red[1] + red[2] + red[3];
    }
}

// ---------------- V transpose + split via smem tiles (coalesced) ----------------
__global__ void v_transpose(const float* __restrict__ vmu, const float* __restrict__ vls,
                            bf16* __restrict__ oh, bf16* __restrict__ ol)
{
    __shared__ float t[32][33];
    const int h = blockIdx.z;
    const int dbase = blockIdx.y * 32;
    const int sbase = blockIdx.x * 32;
    const int tx = threadIdx.x, ty = threadIdx.y;
    const float* src = (dbase < HDn) ? vmu : vls;
    const int dcol = (dbase & (HDn-1)) + tx;
#pragma unroll
    for (int j = 0; j < 4; j++){
        int srow = sbase + ty + j*8;
        t[ty + j*8][tx] = src[(size_t)srow*HIDn + h*HDn + dcol];
    }
    __syncthreads();
#pragma unroll
    for (int j = 0; j < 4; j++){
        int d = dbase + ty + j*8;
        int s = sbase + tx;
        float v = t[tx][ty + j*8];
        size_t off = ((size_t)h*DCn + d)*Sn + s;
        bf16 hh = __float2bfloat16(v);
        oh[off] = hh;
        ol[off] = __float2bfloat16(v - __bfloat162float(hh));
    }
}

// ---------------- row softmax -> split bf16 hi/lo (vectorized) ----------------
__global__ void softmax_split(const float* __restrict__ Pg, bf16* __restrict__ Ph,
                              bf16* __restrict__ Pl)
{
    const float4* p4 = (const float4*)(Pg + (size_t)blockIdx.x * Sn);
    __nv_bfloat162* ph2 = (__nv_bfloat162*)(Ph + (size_t)blockIdx.x * Sn);
    __nv_bfloat162* pl2 = (__nv_bfloat162*)(Pl + (size_t)blockIdx.x * Sn);
    int tid = threadIdx.x;
    float4 x0 = p4[tid], x1 = p4[tid + 256];
    float v[8] = {x0.x, x0.y, x0.z, x0.w, x1.x, x1.y, x1.z, x1.w};
    float m = -1e30f;
#pragma unroll
    for (int i = 0; i < 8; i++) m = fmaxf(m, v[i]);
    __shared__ float redm[8], reds[8];
#pragma unroll
    for (int o = 16; o; o >>= 1) m = fmaxf(m, __shfl_xor_sync(0xffffffffu, m, o));
    if ((tid & 31) == 0) redm[tid>>5] = m;
    __syncthreads();
    if (tid < 32){
        float t = (tid < 8) ? redm[tid] : -1e30f;
#pragma unroll
        for (int o = 4; o; o >>= 1) t = fmaxf(t, __shfl_xor_sync(0xffffffffu, t, o));
        if (tid == 0) redm[0] = t;
    }
    __syncthreads();
    m = redm[0];
    float s = 0.f;
#pragma unroll
    for (int i = 0; i < 8; i++){ v[i] = __expf(v[i] - m); s += v[i]; }
#pragma unroll
    for (int o = 16; o; o >>= 1) s += __shfl_xor_sync(0xffffffffu, s, o);
    if ((tid & 31) == 0) reds[tid>>5] = s;
    __syncthreads();
    if (tid < 32){
        float t = (tid < 8) ? reds[tid] : 0.f;
#pragma unroll
        for (int o = 4; o; o >>= 1) t += __shfl_xor_sync(0xffffffffu, t, o);
        if (tid == 0) reds[0] = t;
    }
    __syncthreads();
    float inv = 1.f / reds[0];
#pragma unroll
    for (int c = 0; c < 2; c++){
#pragma unroll
        for (int pair = 0; pair < 2; pair++){
            float p0 = v[c*4 + pair*2 + 0] * inv;
            float p1 = v[c*4 + pair*2 + 1] * inv;
            uint32_t lo, hi = pack_hi(p0, p1, lo);
            int idx = (c == 0 ? 2*tid : 512 + 2*tid) + pair;
            ph2[idx] = *(__nv_bfloat162*)&hi;
            pl2[idx] = *(__nv_bfloat162*)&lo;
        }
    }
}

// ---------------- launch ----------------
extern "C" void kernel_launch(void* const* d_in, const int* in_sizes, int n_in,
                              void* d_out, int out_size)
{
    const float* xmu  = (const float*)d_in[0];
    const float* xls  = (const float*)d_in[1];
    const float* cosp = (const float*)d_in[2];
    const float* sinp = (const float*)d_in[3];
    const float* tau  = (const float*)d_in[12];
    float* out = (float*)d_out;

    bf16 *Xmu_h, *Xmu_l, *Xls_h, *Xls_l, *Wh, *Wl;
    bf16 *Qh, *Ql, *Kh, *Kl, *Vth, *Vtl, *Ph, *Pl;
    bf16 *Omh, *Oml, *Olh, *Oll;
    float *proj, *P, *kn;
    cudaGetSymbolAddress((void**)&Xmu_h, g_Xmu_h); cudaGetSymbolAddress((void**)&Xmu_l, g_Xmu_l);
    cudaGetSymbolAddress((void**)&Xls_h, g_Xls_h); cudaGetSymbolAddress((void**)&Xls_l, g_Xls_l);
    cudaGetSymbolAddress((void**)&Wh, g_W_h);      cudaGetSymbolAddress((void**)&Wl, g_W_l);
    cudaGetSymbolAddress((void**)&proj, g_proj);
    cudaGetSymbolAddress((void**)&Qh, g_Q_h);  cudaGetSymbolAddress((void**)&Ql, g_Q_l);
    cudaGetSymbolAddress((void**)&Kh, g_K_h);  cudaGetSymbolAddress((void**)&Kl, g_K_l);
    cudaGetSymbolAddress((void**)&Vth, g_Vt_h); cudaGetSymbolAddress((void**)&Vtl, g_Vt_l);
    cudaGetSymbolAddress((void**)&P, g_P);
    cudaGetSymbolAddress((void**)&Ph, g_P_h);  cudaGetSymbolAddress((void**)&Pl, g_P_l);
    cudaGetSymbolAddress((void**)&Omh, g_Om_h); cudaGetSymbolAddress((void**)&Oml, g_Om_l);
    cudaGetSymbolAddress((void**)&Olh, g_Ol_h); cudaGetSymbolAddress((void**)&Oll, g_Ol_l);
    cudaGetSymbolAddress((void**)&kn, g_kn);

    cudaFuncSetAttribute(hm_gemm<E_PROJ6>, cudaFuncAttributeMaxDynamicSharedMemorySize, SMEM_DYN);
    cudaFuncSetAttribute(hm_gemm<E_OUT2>,  cudaFuncAttributeMaxDynamicSharedMemorySize, SMEM_DYN);
    cudaFuncSetAttribute(hm_gemm<E_LOGIT>, cudaFuncAttributeMaxDynamicSharedMemorySize, SMEM_DYN);
    cudaFuncSetAttribute(hm_gemm<E_SPLITPV>,cudaFuncAttributeMaxDynamicSharedMemorySize, SMEM_DYN);

    const int NE = HIDn*HIDn;
    dim3 eb(256);

    split10_v4<<<dim3(NE/(256*8), 10), eb>>>(
        (const float*)d_in[4], (const float*)d_in[5], (const float*)d_in[6], (const float*)d_in[7],
        (const float*)d_in[8], (const float*)d_in[9], (const float*)d_in[10], (const float*)d_in[11],
        xmu, xls,
        Wh, Wl, Xmu_h, Xmu_l, Xls_h, Xls_l);

    dim3 blk(NTHR);
    size_t shm = SMEM_DYN;

    dim3 gp6(HIDn/BNh, Sn/BMh, 6);
    hm_gemm<E_PROJ6><<<gp6, blk, shm>>>(Xmu_h, Xmu_l, Xls_h, Xls_l, Wh, Wl,
        proj, nullptr,nullptr,nullptr,nullptr,
        HIDn, HIDn, HIDn, HIDn, 0,0,0, nullptr, nullptr);

    qk_transform2<<<dim3(Sn, NHn, 2), 128>>>(proj, cosp, sinp, Qh, Ql, Kh, Kl, kn);
    v_transpose<<<dim3(Sn/32, DCn/32, NHn), dim3(32,8)>>>(proj + 2*(size_t)Sn*HIDn, proj + 5*(size_t)Sn*HIDn, Vth, Vtl);

    dim3 gl(Sn/BNh, Sn/BMh, NHn);
    hm_gemm<E_LOGIT><<<gl, blk, shm>>>(Qh, Ql, nullptr, nullptr, Kh, Kl, P,
        nullptr,nullptr,nullptr,nullptr,
        DCn, DCn, DCn, Sn,
        (long long)Sn*DCn, (long long)Sn*DCn, (long long)Sn*Sn, kn, tau);

    softmax_split<<<NHn*Sn, 256>>>(P, Ph, Pl);

    dim3 gv(DCn/BNh, Sn/BMh, NHn);
    hm_gemm<E_SPLITPV><<<gv, blk, shm>>>(Ph, Pl, nullptr, nullptr, Vth, Vtl, nullptr,
        Omh, Oml, Olh, Oll,
        Sn, Sn, Sn, HIDn,
        (long long)Sn*Sn, (long long)DCn*Sn, 0, nullptr, nullptr);

    dim3 go2(HIDn/BNh, Sn/BMh, 2);
    hm_gemm<E_OUT2><<<go2, blk, shm>>>(Omh, Oml, Olh, Oll, Wh, Wl,
        out, nullptr,nullptr,nullptr,nullptr,
        HIDn, HIDn, HIDn, HIDn, 0,0,0, nullptr, nullptr);
}

// round 16
// speedup vs baseline: 1.0298x; 1.0298x over previous
#include <cuda_runtime.h>
#include <cuda_bf16.h>
#include <math.h>
#include <stdint.h>

typedef __nv_bfloat16 bf16;

#define Sn   2048
#define HIDn 2048
#define NHn  16
#define HDn  128
#define DCn  256

#define BMh  128
#define BNh  128
#define BKh  32
#define NTHR 256
#define ROWB 64
#define TILE_B (BMh * ROWB)            // 8KB per operand tile
#define STAGE_B (4 * TILE_B)           // Ah, Al, Bh, Bl = 32KB per stage
#define NSTAGE 3
#define SMEM_DYN (NSTAGE * STAGE_B)    // 96KB

// ---------------- device globals (scratch) ----------------
static __device__ __align__(1024) bf16 g_Xmu_h[Sn*HIDn], g_Xmu_l[Sn*HIDn];
static __device__ __align__(1024) bf16 g_Xls_h[Sn*HIDn], g_Xls_l[Sn*HIDn];
static __device__ __align__(1024) bf16 g_W_h[8][HIDn*HIDn];
static __device__ __align__(1024) bf16 g_W_l[8][HIDn*HIDn];
static __device__ __align__(1024) float g_proj[6][(size_t)Sn*HIDn];
static __device__ __align__(1024) bf16 g_Q_h[(size_t)NHn*Sn*DCn], g_Q_l[(size_t)NHn*Sn*DCn];
static __device__ __align__(1024) bf16 g_K_h[(size_t)NHn*Sn*DCn], g_K_l[(size_t)NHn*Sn*DCn];
static __device__ __align__(1024) bf16 g_Vt_h[(size_t)NHn*DCn*Sn], g_Vt_l[(size_t)NHn*DCn*Sn];
static __device__ __align__(1024) float g_P[(size_t)NHn*Sn*Sn];
static __device__ __align__(1024) bf16 g_P_h[(size_t)NHn*Sn*Sn], g_P_l[(size_t)NHn*Sn*Sn];
static __device__ __align__(1024) bf16 g_Om_h[Sn*HIDn], g_Om_l[Sn*HIDn];
static __device__ __align__(1024) bf16 g_Ol_h[Sn*HIDn], g_Ol_l[Sn*HIDn];
static __device__ float g_kn[NHn*Sn];

// ---------------- helpers ----------------
__device__ __forceinline__ uint32_t smem_u32(const void* p){
    uint32_t a;
    asm("{ .reg .u64 t; cvta.to.shared.u64 t, %1; cvt.u32.u64 %0, t; }" : "=r"(a) : "l"(p));
    return a;
}
__device__ __forceinline__ void cp16(uint32_t dst, const void* src){
    asm volatile("cp.async.cg.shared.global [%0], [%1], 16;" :: "r"(dst), "l"(src) : "memory");
}
#define CP_COMMIT() asm volatile("cp.async.commit_group;" ::: "memory")
#define CP_WAIT1()  asm volatile("cp.async.wait_group 1;" ::: "memory")

__device__ __forceinline__ void ldsm4(uint32_t* r, uint32_t addr){
    asm volatile("ldmatrix.sync.aligned.m8n8.x4.shared.b16 {%0,%1,%2,%3}, [%4];"
                 : "=r"(r[0]), "=r"(r[1]), "=r"(r[2]), "=r"(r[3]) : "r"(addr));
}
__device__ __forceinline__ void hmma(float* d, const uint32_t* a, uint32_t b0, uint32_t b1){
    asm volatile("mma.sync.aligned.m16n8k16.row.col.f32.bf16.bf16.f32 "
                 "{%0,%1,%2,%3}, {%4,%5,%6,%7}, {%8,%9}, {%0,%1,%2,%3};"
                 : "+f"(d[0]), "+f"(d[1]), "+f"(d[2]), "+f"(d[3])
                 : "r"(a[0]), "r"(a[1]), "r"(a[2]), "r"(a[3]), "r"(b0), "r"(b1));
}
__device__ __forceinline__ uint32_t sw_off(int row, int chunk){
    return (uint32_t)(row * ROWB + ((chunk ^ ((row >> 1) & 3)) << 4));
}
__device__ __forceinline__ uint32_t pack_hi(float a, float b, uint32_t& lo){
    bf16 h0 = __float2bfloat16(a), h1 = __float2bfloat16(b);
    __nv_bfloat162 hh; hh.x = h0; hh.y = h1;
    __nv_bfloat162 ll;
    ll.x = __float2bfloat16(a - __bfloat162float(h0));
    ll.y = __float2bfloat16(b - __bfloat162float(h1));
    lo = *(uint32_t*)&ll;
    return *(uint32_t*)&hh;
}

// ---------------- 4-tile stage loader ----------------
__device__ __forceinline__ void load_stage4(uint32_t st,
    const bf16* __restrict__ Ah, const bf16* __restrict__ Al,
    const bf16* __restrict__ Bh, const bf16* __restrict__ Bl,
    int lda, int ldb, int koff, int tid)
{
#pragma unroll
    for (int i = 0; i < 8; i++){
        const int tile = i >> 1;
        const int id = tid + i*NTHR;
        const int r = (id >> 2) & 127;
        const int c = id & 3;
        const bf16* base = (tile==0) ? Ah : (tile==1) ? Al : (tile==2) ? Bh : Bl;
        const int ld = (tile < 2) ? lda : ldb;
        cp16(st + tile*TILE_B + sw_off(r, c), base + (size_t)r*ld + koff + c*8);
    }
    CP_COMMIT();
}

enum { E_LOGIT = 1, E_SPLITPV = 2, E_PROJ6 = 3, E_OUT2 = 4 };

// ---------------- HMMA GEMM: C[M,N] = (Ah+Al)(Bh+Bl)^T via bf16x3 ----------------
// (R10/R14 mainloop — measured local optimum; frozen.)
template<int MODE>
__global__ void __launch_bounds__(NTHR, 2)
hm_gemm(const bf16* __restrict__ Ah, const bf16* __restrict__ Al,
        const bf16* __restrict__ A2h, const bf16* __restrict__ A2l,
        const bf16* __restrict__ WhB, const bf16* __restrict__ WlB,
        float* __restrict__ C,
        bf16* __restrict__ OH, bf16* __restrict__ OL,
        bf16* __restrict__ OH2, bf16* __restrict__ OL2,
        int K, int lda, int ldb, int ldc,
        long long sA, long long sB, long long sC,
        const float* __restrict__ knArr, const float* __restrict__ tau)
{
    extern __shared__ __align__(128) char smem[];
    const uint32_t sb = smem_u32(smem);
    const int tid  = threadIdx.x;
    const int lane = tid & 31;
    const int wid  = tid >> 5;
    const int wm = wid & 3;
    const int wn = wid >> 2;
    const int z = blockIdx.z;
    const int mbase = blockIdx.y * BMh, nbase = blockIdx.x * BNh;

    const bf16 *bAh, *bAl, *bBh, *bBl;
    float* Cz = C;
    if (MODE == E_PROJ6){
        const bool ls = (z >= 3);
        bAh = ls ? A2h : Ah;  bAl = ls ? A2l : Al;
        const int wsel = ls ? (z + 1) : z;
        bBh = WhB + (size_t)wsel*HIDn*HIDn;
        bBl = WlB + (size_t)wsel*HIDn*HIDn;
        Cz = C + (size_t)z*Sn*HIDn;
    } else if (MODE == E_OUT2){
        bAh = z ? A2h : Ah;  bAl = z ? A2l : Al;
        const int wsel = z ? 7 : 3;
        bBh = WhB + (size_t)wsel*HIDn*HIDn;
        bBl = WlB + (size_t)wsel*HIDn*HIDn;
        Cz = C + (size_t)z*Sn*HIDn;
    } else {
        bAh = Ah + (size_t)z*sA;  bAl = Al + (size_t)z*sA;
        bBh = WhB + (size_t)z*sB; bBl = WlB + (size_t)z*sB;
        Cz = C + (size_t)z*sC;
    }
    const bf16* pAh = bAh + (size_t)mbase*lda;
    const bf16* pAl = bAl + (size_t)mbase*lda;
    const bf16* pBh = bBh + (size_t)nbase*ldb;
    const bf16* pBl = bBl + (size_t)nbase*ldb;

    const int kbn = K / BKh;

    float acc[2][8][4];
#pragma unroll
    for (int i = 0; i < 2; i++)
#pragma unroll
        for (int j = 0; j < 8; j++)
#pragma unroll
            for (int q = 0; q < 4; q++) acc[i][j][q] = 0.f;

    const int aRow = wm*32 + (lane & 7) + 8*((lane >> 3) & 1);
    const int aChk = lane >> 4;
    const int bRow = wn*64 + (lane & 7) + 8*(lane >> 4);
    const int bChk = (lane >> 3) & 1;

    load_stage4(sb + 0*STAGE_B, pAh, pAl, pBh, pBl, lda, ldb, 0,   tid);
    load_stage4(sb + 1*STAGE_B, pAh, pAl, pBh, pBl, lda, ldb, BKh, tid);

    int stidx = 0;
    for (int kb = 0; kb < kbn; kb++){
        const uint32_t aTh = sb + stidx*STAGE_B;
        const uint32_t aTl = aTh + TILE_B;
        const uint32_t bTh = aTh + 2*TILE_B;
        const uint32_t bTl = aTh + 3*TILE_B;
        CP_WAIT1();
        __syncthreads();

#pragma unroll
        for (int s = 0; s < 2; s++){
            uint32_t ah[2][4], al[2][4], bh[4][4], bl[4][4];
#pragma unroll
            for (int mt = 0; mt < 2; mt++)
                ldsm4(ah[mt], aTh + sw_off(aRow + mt*16, 2*s + aChk));
#pragma unroll
            for (int np = 0; np < 4; np++)
                ldsm4(bh[np], bTh + sw_off(bRow + np*16, 2*s + bChk));
#pragma unroll
            for (int mt = 0; mt < 2; mt++)
#pragma unroll
                for (int nt = 0; nt < 8; nt++){
                    const uint32_t* bb = bh[nt >> 1];
                    const int o = (nt & 1) * 2;
                    hmma(acc[mt][nt], ah[mt], bb[o], bb[o+1]);
                }
#pragma unroll
            for (int mt = 0; mt < 2; mt++)
                ldsm4(al[mt], aTl + sw_off(aRow + mt*16, 2*s + aChk));
#pragma unroll
            for (int mt = 0; mt < 2; mt++)
#pragma unroll
                for (int nt = 0; nt < 8; nt++){
                    const uint32_t* bb = bh[nt >> 1];
                    const int o = (nt & 1) * 2;
                    hmma(acc[mt][nt], al[mt], bb[o], bb[o+1]);
                }
#pragma unroll
            for (int np = 0; np < 4; np++)
                ldsm4(bl[np], bTl + sw_off(bRow + np*16, 2*s + bChk));
#pragma unroll
            for (int mt = 0; mt < 2; mt++)
#pragma unroll
                for (int nt = 0; nt < 8; nt++){
                    const uint32_t* bb = bl[nt >> 1];
                    const int o = (nt & 1) * 2;
                    hmma(acc[mt][nt], ah[mt], bb[o], bb[o+1]);
                }
        }
        if (kb + 2 < kbn){
            const int nidx = (stidx + 2 >= NSTAGE) ? stidx + 2 - NSTAGE : stidx + 2;
            load_stage4(sb + nidx*STAGE_B, pAh, pAl, pBh, pBl, lda, ldb, (kb+2)*BKh, tid);
        }
        stidx = (stidx + 1 == NSTAGE) ? 0 : stidx + 1;
    }

    // epilogue
    float invden = 1.0f;
    const float* knz = nullptr;
    if (MODE == E_LOGIT){
        invden = 1.0f / (fabsf(tau[0]) + 1e-6f);
        knz = knArr + (size_t)z * Sn;
    }
    const int rr = lane >> 2;
    const int cc = (lane & 3) * 2;
#pragma unroll
    for (int mt = 0; mt < 2; mt++){
#pragma unroll
        for (int nt = 0; nt < 8; nt++){
#pragma unroll
            for (int half = 0; half < 2; half++){
                int grow = mbase + wm*32 + mt*16 + rr + half*8;
                int gcol = nbase + wn*64 + nt*8 + cc;
                float v0 = acc[mt][nt][half*2 + 0];
                float v1 = acc[mt][nt][half*2 + 1];
                if (MODE == E_LOGIT){
                    v0 = (2.0f*v0 - knz[gcol])   * invden;
                    v1 = (2.0f*v1 - knz[gcol+1]) * invden;
                }
                if (MODE == E_SPLITPV){
                    bf16* dh = (nbase < HDn) ? OH : OH2;
                    bf16* dl = (nbase < HDn) ? OL : OL2;
                    size_t off = (size_t)grow*HIDn + (size_t)z*HDn + (gcol & (HDn-1));
                    uint32_t lo, hi = pack_hi(v0, v1, lo);
                    *(uint32_t*)(dh + off) = hi;
                    *(uint32_t*)(dl + off) = lo;
                } else {
                    float2 vv = make_float2(v0, v1);
                    float* dst = Cz + (size_t)grow*ldc + gcol;
                    *(float2*)dst = vv;
                }
            }
        }
    }
}

// ---------------- merged split: 10 matrices (8 W + xmu + xls), 8 elems/thread ---
__global__ void split10_v4(const float* __restrict__ w0, const float* __restrict__ w1,
                           const float* __restrict__ w2, const float* __restrict__ w3,
                           const float* __restrict__ w4, const float* __restrict__ w5,
                           const float* __restrict__ w6, const float* __restrict__ w7,
                           const float* __restrict__ xmu, const float* __restrict__ xls,
                           bf16* __restrict__ Wh, bf16* __restrict__ Wl,
                           bf16* __restrict__ Xmuh, bf16* __restrict__ Xmul,
                           bf16* __restrict__ Xlsh, bf16* __restrict__ Xlsl)
{
    const int w = blockIdx.y;
    const float* src;
    bf16 *dh, *dl;
    switch (w){
        case 0: src = w0;  dh = Wh + 0*(size_t)HIDn*HIDn; dl = Wl + 0*(size_t)HIDn*HIDn; break;
        case 1: src = w1;  dh = Wh + 1*(size_t)HIDn*HIDn; dl = Wl + 1*(size_t)HIDn*HIDn; break;
        case 2: src = w2;  dh = Wh + 2*(size_t)HIDn*HIDn; dl = Wl + 2*(size_t)HIDn*HIDn; break;
        case 3: src = w3;  dh = Wh + 3*(size_t)HIDn*HIDn; dl = Wl + 3*(size_t)HIDn*HIDn; break;
        case 4: src = w4;  dh = Wh + 4*(size_t)HIDn*HIDn; dl = Wl + 4*(size_t)HIDn*HIDn; break;
        case 5: src = w5;  dh = Wh + 5*(size_t)HIDn*HIDn; dl = Wl + 5*(size_t)HIDn*HIDn; break;
        case 6: src = w6;  dh = Wh + 6*(size_t)HIDn*HIDn; dl = Wl + 6*(size_t)HIDn*HIDn; break;
        case 7: src = w7;  dh = Wh + 7*(size_t)HIDn*HIDn; dl = Wl + 7*(size_t)HIDn*HIDn; break;
        case 8: src = xmu; dh = Xmuh; dl = Xmul; break;
        default: src = xls; dh = Xlsh; dl = Xlsl; break;
    }
    size_t i = (size_t)blockIdx.x*blockDim.x + threadIdx.x;
    const float4* in = (const float4*)src;
    float4 a = in[2*i], b = in[2*i + 1];
    float va[8] = {a.x, a.y, a.z, a.w, b.x, b.y, b.z, b.w};
    uint32_t hw[4], lw[4];
#pragma unroll
    for (int p = 0; p < 4; p++)
        hw[p] = pack_hi(va[2*p], va[2*p+1], lw[p]);
    ((uint4*)dh)[i] = make_uint4(hw[0], hw[1], hw[2], hw[3]);
    ((uint4*)dl)[i] = make_uint4(lw[0], lw[1], lw[2], lw[3]);
}

// ---------------- merged Q/K transform: rope + exp + split + kn(K only) ---------
__global__ void qk_transform2(const float* __restrict__ projBase,
                              const float* __restrict__ cosp, const float* __restrict__ sinp,
                              bf16* __restrict__ Qh, bf16* __restrict__ Ql,
                              bf16* __restrict__ Kh, bf16* __restrict__ Kl,
                              float* __restrict__ kn)
{
    const int which = blockIdx.z;
    const float* mu = projBase + (size_t)which     *Sn*HIDn;
    const float* ls = projBase + (size_t)(which+3) *Sn*HIDn;
    bf16* oh = which ? Kh : Qh;
    bf16* ol = which ? Kl : Ql;
    int s = blockIdx.x, h = blockIdx.y, d = threadIdx.x;
    size_t ib = (size_t)s*HIDn + h*HDn;
    float m = mu[ib + d];
    float o = mu[ib + ((d < 64) ? d + 64 : d - 64)];
    float c = cosp[s*HDn + d], sv = sinp[s*HDn + d];
    float roped = (d < 64) ? (m*c - o*sv) : (m*c + o*sv);
    float sg = expf(0.5f * ls[ib + d]);
    size_t ob = ((size_t)h*Sn + s)*DCn;
    bf16 hh = __float2bfloat16(roped);
    oh[ob + d] = hh; ol[ob + d] = __float2bfloat16(roped - __bfloat162float(hh));
    bf16 hs = __float2bfloat16(sg);
    oh[ob + 128 + d] = hs; ol[ob + 128 + d] = __float2bfloat16(sg - __bfloat162float(hs));
    if (which == 1){
        float acc = roped*roped + sg*sg;
#pragma unroll
        for (int off = 16; off; off >>= 1) acc += __shfl_xor_sync(0xffffffffu, acc, off);
        __shared__ float red[4];
        if ((d & 31) == 0) red[d>>5] = acc;
        __syncthreads();
        if (d == 0) kn[(size_t)h*Sn + s] = red[0] + red[1] + red[2] + red[3];
    }
}

// ---------------- V transpose + split via smem tiles (coalesced) ----------------
__global__ void v_transpose(const float* __restrict__ vmu, const float* __restrict__ vls,
                            bf16* __restrict__ oh, bf16* __restrict__ ol)
{
    __shared__ float t[32][33];
    const int h = blockIdx.z;
    const int dbase = blockIdx.y * 32;
    const int sbase = blockIdx.x * 32;
    const int tx = threadIdx.x, ty = threadIdx.y;
    const float* src = (dbase < HDn) ? vmu : vls;
    const int dcol = (dbase & (HDn-1)) + tx;
#pragma unroll
    for (int j = 0; j < 4; j++){
        int srow = sbase + ty + j*8;
        t[ty + j*8][tx] = src[(size_t)srow*HIDn + h*HDn + dcol];
    }
    __syncthreads();
#pragma unroll
    for (int j = 0; j < 4; j++){
        int d = dbase + ty + j*8;
        int s = sbase + tx;
        float v = t[tx][ty + j*8];
        size_t off = ((size_t)h*DCn + d)*Sn + s;
        bf16 hh = __float2bfloat16(v);
        oh[off] = hh;
        ol[off] = __float2bfloat16(v - __bfloat162float(hh));
    }
}

// ---------------- row softmax -> split bf16 hi/lo (vectorized) ----------------
__global__ void softmax_split(const float* __restrict__ Pg, bf16* __restrict__ Ph,
                              bf16* __restrict__ Pl)
{
    const float4* p4 = (const float4*)(Pg + (size_t)blockIdx.x * Sn);
    __nv_bfloat162* ph2 = (__nv_bfloat162*)(Ph + (size_t)blockIdx.x * Sn);
    __nv_bfloat162* pl2 = (__nv_bfloat162*)(Pl + (size_t)blockIdx.x * Sn);
    int tid = threadIdx.x;
    float4 x0 = p4[tid], x1 = p4[tid + 256];
    float v[8] = {x0.x, x0.y, x0.z, x0.w, x1.x, x1.y, x1.z, x1.w};
    float m = -1e30f;
#pragma unroll
    for (int i = 0; i < 8; i++) m = fmaxf(m, v[i]);
    __shared__ float redm[8], reds[8];
#pragma unroll
    for (int o = 16; o; o >>= 1) m = fmaxf(m, __shfl_xor_sync(0xffffffffu, m, o));
    if ((tid & 31) == 0) redm[tid>>5] = m;
    __syncthreads();
    if (tid < 32){
        float t = (tid < 8) ? redm[tid] : -1e30f;
#pragma unroll
        for (int o = 4; o; o >>= 1) t = fmaxf(t, __shfl_xor_sync(0xffffffffu, t, o));
        if (tid == 0) redm[0] = t;
    }
    __syncthreads();
    m = redm[0];
    float s = 0.f;
#pragma unroll
    for (int i = 0; i < 8; i++){ v[i] = __expf(v[i] - m); s += v[i]; }
#pragma unroll
    for (int o = 16; o; o >>= 1) s += __shfl_xor_sync(0xffffffffu, s, o);
    if ((tid & 31) == 0) reds[tid>>5] = s;
    __syncthreads();
    if (tid < 32){
        float t = (tid < 8) ? reds[tid] : 0.f;
#pragma unroll
        for (int o = 4; o; o >>= 1) t += __shfl_xor_sync(0xffffffffu, t, o);
        if (tid == 0) reds[0] = t;
    }
    __syncthreads();
    float inv = 1.f / reds[0];
#pragma unroll
    for (int c = 0; c < 2; c++){
#pragma unroll
        for (int pair = 0; pair < 2; pair++){
            float p0 = v[c*4 + pair*2 + 0] * inv;
            float p1 = v[c*4 + pair*2 + 1] * inv;
            uint32_t lo, hi = pack_hi(p0, p1, lo);
            int idx = (c == 0 ? 2*tid : 512 + 2*tid) + pair;
            ph2[idx] = *(__nv_bfloat162*)&hi;
            pl2[idx] = *(__nv_bfloat162*)&lo;
        }
    }
}

// ---------------- launch ----------------
extern "C" void kernel_launch(void* const* d_in, const int* in_sizes, int n_in,
                              void* d_out, int out_size)
{
    const float* xmu  = (const float*)d_in[0];
    const float* xls  = (const float*)d_in[1];
    const float* cosp = (const float*)d_in[2];
    const float* sinp = (const float*)d_in[3];
    const float* tau  = (const float*)d_in[12];
    float* out = (float*)d_out;

    bf16 *Xmu_h, *Xmu_l, *Xls_h, *Xls_l, *Wh, *Wl;
    bf16 *Qh, *Ql, *Kh, *Kl, *Vth, *Vtl, *Ph, *Pl;
    bf16 *Omh, *Oml, *Olh, *Oll;
    float *proj, *P, *kn;
    cudaGetSymbolAddress((void**)&Xmu_h, g_Xmu_h); cudaGetSymbolAddress((void**)&Xmu_l, g_Xmu_l);
    cudaGetSymbolAddress((void**)&Xls_h, g_Xls_h); cudaGetSymbolAddress((void**)&Xls_l, g_Xls_l);
    cudaGetSymbolAddress((void**)&Wh, g_W_h);      cudaGetSymbolAddress((void**)&Wl, g_W_l);
    cudaGetSymbolAddress((void**)&proj, g_proj);
    cudaGetSymbolAddress((void**)&Qh, g_Q_h);  cudaGetSymbolAddress((void**)&Ql, g_Q_l);
    cudaGetSymbolAddress((void**)&Kh, g_K_h);  cudaGetSymbolAddress((void**)&Kl, g_K_l);
    cudaGetSymbolAddress((void**)&Vth, g_Vt_h); cudaGetSymbolAddress((void**)&Vtl, g_Vt_l);
    cudaGetSymbolAddress((void**)&P, g_P);
    cudaGetSymbolAddress((void**)&Ph, g_P_h);  cudaGetSymbolAddress((void**)&Pl, g_P_l);
    cudaGetSymbolAddress((void**)&Omh, g_Om_h); cudaGetSymbolAddress((void**)&Oml, g_Om_l);
    cudaGetSymbolAddress((void**)&Olh, g_Ol_h); cudaGetSymbolAddress((void**)&Oll, g_Ol_l);
    cudaGetSymbolAddress((void**)&kn, g_kn);

    cudaFuncSetAttribute(hm_gemm<E_PROJ6>, cudaFuncAttributeMaxDynamicSharedMemorySize, SMEM_DYN);
    cudaFuncSetAttribute(hm_gemm<E_OUT2>,  cudaFuncAttributeMaxDynamicSharedMemorySize, SMEM_DYN);
    cudaFuncSetAttribute(hm_gemm<E_LOGIT>, cudaFuncAttributeMaxDynamicSharedMemorySize, SMEM_DYN);
    cudaFuncSetAttribute(hm_gemm<E_SPLITPV>,cudaFuncAttributeMaxDynamicSharedMemorySize, SMEM_DYN);

    const int NE = HIDn*HIDn;
    dim3 eb(256);

    split10_v4<<<dim3(NE/(256*8), 10), eb>>>(
        (const float*)d_in[4], (const float*)d_in[5], (const float*)d_in[6], (const float*)d_in[7],
        (const float*)d_in[8], (const float*)d_in[9], (const float*)d_in[10], (const float*)d_in[11],
        xmu, xls,
        Wh, Wl, Xmu_h, Xmu_l, Xls_h, Xls_l);

    dim3 blk(NTHR);
    size_t shm = SMEM_DYN;

    dim3 gp6(HIDn/BNh, Sn/BMh, 6);
    hm_gemm<E_PROJ6><<<gp6, blk, shm>>>(Xmu_h, Xmu_l, Xls_h, Xls_l, Wh, Wl,
        proj, nullptr,nullptr,nullptr,nullptr,
        HIDn, HIDn, HIDn, HIDn, 0,0,0, nullptr, nullptr);

    qk_transform2<<<dim3(Sn, NHn, 2), 128>>>(proj, cosp, sinp, Qh, Ql, Kh, Kl, kn);
    v_transpose<<<dim3(Sn/32, DCn/32, NHn), dim3(32,8)>>>(proj + 2*(size_t)Sn*HIDn, proj + 5*(size_t)Sn*HIDn, Vth, Vtl);

    dim3 gl(Sn/BNh, Sn/BMh, NHn);
    hm_gemm<E_LOGIT><<<gl, blk, shm>>>(Qh, Ql, nullptr, nullptr, Kh, Kl, P,
        nullptr,nullptr,nullptr,nullptr,
        DCn, DCn, DCn, Sn,
        (long long)Sn*DCn, (long long)Sn*DCn, (long long)Sn*Sn, kn, tau);

    softmax_split<<<NHn*Sn, 256>>>(P, Ph, Pl);

    dim3 gv(DCn/BNh, Sn/BMh, NHn);
    hm_gemm<E_SPLITPV><<<gv, blk, shm>>>(Ph, Pl, nullptr, nullptr, Vth, Vtl, nullptr,
        Omh, Oml, Olh, Oll,
        Sn, Sn, Sn, HIDn,
        (long long)Sn*Sn, (long long)DCn*Sn, 0, nullptr, nullptr);

    dim3 go2(HIDn/BNh, Sn/BMh, 2);
    hm_gemm<E_OUT2><<<go2, blk, shm>>>(Omh, Oml, Olh, Oll, Wh, Wl,
        out, nullptr,nullptr,nullptr,nullptr,
        HIDn, HIDn, HIDn, HIDn, 0,0,0, nullptr, nullptr);
}

// round 17
// speedup vs baseline: 1.0321x; 1.0022x over previous
#include <cuda_runtime.h>
#include <cuda_bf16.h>
#include <math.h>
#include <stdint.h>

typedef __nv_bfloat16 bf16;

#define Sn   2048
#define HIDn 2048
#define NHn  16
#define HDn  128
#define DCn  256

#define BMh  128
#define BNh  128
#define BKh  32
#define NTHR 256
#define ROWB 64
#define TILE_B (BMh * ROWB)            // 8KB per operand tile
#define STAGE_B (4 * TILE_B)           // Ah, Al, Bh, Bl = 32KB per stage
#define NSTAGE 3
#define SMEM_DYN (NSTAGE * STAGE_B)    // 96KB

// ---------------- device globals (scratch) ----------------
static __device__ __align__(1024) bf16 g_Xmu_h[Sn*HIDn], g_Xmu_l[Sn*HIDn];
static __device__ __align__(1024) bf16 g_Xls_h[Sn*HIDn], g_Xls_l[Sn*HIDn];
static __device__ __align__(1024) bf16 g_W_h[8][HIDn*HIDn];
static __device__ __align__(1024) bf16 g_W_l[8][HIDn*HIDn];
static __device__ __align__(1024) float g_proj[6][(size_t)Sn*HIDn];
static __device__ __align__(1024) bf16 g_Q_h[(size_t)NHn*Sn*DCn], g_Q_l[(size_t)NHn*Sn*DCn];
static __device__ __align__(1024) bf16 g_K_h[(size_t)NHn*Sn*DCn], g_K_l[(size_t)NHn*Sn*DCn];
static __device__ __align__(1024) bf16 g_Vt_h[(size_t)NHn*DCn*Sn], g_Vt_l[(size_t)NHn*DCn*Sn];
static __device__ __align__(1024) float g_P[(size_t)NHn*Sn*Sn];
static __device__ __align__(1024) bf16 g_P_h[(size_t)NHn*Sn*Sn], g_P_l[(size_t)NHn*Sn*Sn];
static __device__ __align__(1024) bf16 g_Om_h[Sn*HIDn], g_Om_l[Sn*HIDn];
static __device__ __align__(1024) bf16 g_Ol_h[Sn*HIDn], g_Ol_l[Sn*HIDn];
static __device__ float g_kn[NHn*Sn];

// ---------------- helpers ----------------
__device__ __forceinline__ uint32_t smem_u32(const void* p){
    uint32_t a;
    asm("{ .reg .u64 t; cvta.to.shared.u64 t, %1; cvt.u32.u64 %0, t; }" : "=r"(a) : "l"(p));
    return a;
}
__device__ __forceinline__ void cp16(uint32_t dst, const void* src){
    asm volatile("cp.async.cg.shared.global [%0], [%1], 16;" :: "r"(dst), "l"(src) : "memory");
}
#define CP_COMMIT() asm volatile("cp.async.commit_group;" ::: "memory")
#define CP_WAIT1()  asm volatile("cp.async.wait_group 1;" ::: "memory")

__device__ __forceinline__ void ldsm4(uint32_t* r, uint32_t addr){
    asm volatile("ldmatrix.sync.aligned.m8n8.x4.shared.b16 {%0,%1,%2,%3}, [%4];"
                 : "=r"(r[0]), "=r"(r[1]), "=r"(r[2]), "=r"(r[3]) : "r"(addr));
}
__device__ __forceinline__ void hmma(float* d, const uint32_t* a, uint32_t b0, uint32_t b1){
    asm volatile("mma.sync.aligned.m16n8k16.row.col.f32.bf16.bf16.f32 "
                 "{%0,%1,%2,%3}, {%4,%5,%6,%7}, {%8,%9}, {%0,%1,%2,%3};"
                 : "+f"(d[0]), "+f"(d[1]), "+f"(d[2]), "+f"(d[3])
                 : "r"(a[0]), "r"(a[1]), "r"(a[2]), "r"(a[3]), "r"(b0), "r"(b1));
}
__device__ __forceinline__ uint32_t sw_off(int row, int chunk){
    return (uint32_t)(row * ROWB + ((chunk ^ ((row >> 1) & 3)) << 4));
}
__device__ __forceinline__ uint32_t pack_hi(float a, float b, uint32_t& lo){
    bf16 h0 = __float2bfloat16(a), h1 = __float2bfloat16(b);
    __nv_bfloat162 hh; hh.x = h0; hh.y = h1;
    __nv_bfloat162 ll;
    ll.x = __float2bfloat16(a - __bfloat162float(h0));
    ll.y = __float2bfloat16(b - __bfloat162float(h1));
    lo = *(uint32_t*)&ll;
    return *(uint32_t*)&hh;
}

// ---------------- 4-tile stage loader ----------------
__device__ __forceinline__ void load_stage4(uint32_t st,
    const bf16* __restrict__ Ah, const bf16* __restrict__ Al,
    const bf16* __restrict__ Bh, const bf16* __restrict__ Bl,
    int lda, int ldb, int koff, int tid)
{
#pragma unroll
    for (int i = 0; i < 8; i++){
        const int tile = i >> 1;
        const int id = tid + i*NTHR;
        const int r = (id >> 2) & 127;
        const int c = id & 3;
        const bf16* base = (tile==0) ? Ah : (tile==1) ? Al : (tile==2) ? Bh : Bl;
        const int ld = (tile < 2) ? lda : ldb;
        cp16(st + tile*TILE_B + sw_off(r, c), base + (size_t)r*ld + koff + c*8);
    }
    CP_COMMIT();
}

enum { E_LOGIT = 1, E_SPLITPV = 2, E_PROJ6 = 3, E_OUT2 = 4 };

// ---------------- HMMA GEMM: C[M,N] = (Ah+Al)(Bh+Bl)^T via bf16x3 ----------------
// (R10/R14 mainloop — measured local optimum; frozen.)
template<int MODE>
__global__ void __launch_bounds__(NTHR, 2)
hm_gemm(const bf16* __restrict__ Ah, const bf16* __restrict__ Al,
        const bf16* __restrict__ A2h, const bf16* __restrict__ A2l,
        const bf16* __restrict__ WhB, const bf16* __restrict__ WlB,
        float* __restrict__ C,
        bf16* __restrict__ OH, bf16* __restrict__ OL,
        bf16* __restrict__ OH2, bf16* __restrict__ OL2,
        int K, int lda, int ldb, int ldc,
        long long sA, long long sB, long long sC,
        const float* __restrict__ knArr, const float* __restrict__ tau)
{
    extern __shared__ __align__(128) char smem[];
    const uint32_t sb = smem_u32(smem);
    const int tid  = threadIdx.x;
    const int lane = tid & 31;
    const int wid  = tid >> 5;
    const int wm = wid & 3;
    const int wn = wid >> 2;
    const int z = blockIdx.z;
    const int mbase = blockIdx.y * BMh, nbase = blockIdx.x * BNh;

    const bf16 *bAh, *bAl, *bBh, *bBl;
    float* Cz = C;
    if (MODE == E_PROJ6){
        const bool ls = (z >= 3);
        bAh = ls ? A2h : Ah;  bAl = ls ? A2l : Al;
        const int wsel = ls ? (z + 1) : z;
        bBh = WhB + (size_t)wsel*HIDn*HIDn;
        bBl = WlB + (size_t)wsel*HIDn*HIDn;
        Cz = C + (size_t)z*Sn*HIDn;
    } else if (MODE == E_OUT2){
        bAh = z ? A2h : Ah;  bAl = z ? A2l : Al;
        const int wsel = z ? 7 : 3;
        bBh = WhB + (size_t)wsel*HIDn*HIDn;
        bBl = WlB + (size_t)wsel*HIDn*HIDn;
        Cz = C + (size_t)z*Sn*HIDn;
    } else {
        bAh = Ah + (size_t)z*sA;  bAl = Al + (size_t)z*sA;
        bBh = WhB + (size_t)z*sB; bBl = WlB + (size_t)z*sB;
        Cz = C + (size_t)z*sC;
    }
    const bf16* pAh = bAh + (size_t)mbase*lda;
    const bf16* pAl = bAl + (size_t)mbase*lda;
    const bf16* pBh = bBh + (size_t)nbase*ldb;
    const bf16* pBl = bBl + (size_t)nbase*ldb;

    const int kbn = K / BKh;

    float acc[2][8][4];
#pragma unroll
    for (int i = 0; i < 2; i++)
#pragma unroll
        for (int j = 0; j < 8; j++)
#pragma unroll
            for (int q = 0; q < 4; q++) acc[i][j][q] = 0.f;

    const int aRow = wm*32 + (lane & 7) + 8*((lane >> 3) & 1);
    const int aChk = lane >> 4;
    const int bRow = wn*64 + (lane & 7) + 8*(lane >> 4);
    const int bChk = (lane >> 3) & 1;

    load_stage4(sb + 0*STAGE_B, pAh, pAl, pBh, pBl, lda, ldb, 0,   tid);
    load_stage4(sb + 1*STAGE_B, pAh, pAl, pBh, pBl, lda, ldb, BKh, tid);

    int stidx = 0;
    for (int kb = 0; kb < kbn; kb++){
        const uint32_t aTh = sb + stidx*STAGE_B;
        const uint32_t aTl = aTh + TILE_B;
        const uint32_t bTh = aTh + 2*TILE_B;
        const uint32_t bTl = aTh + 3*TILE_B;
        CP_WAIT1();
        __syncthreads();

#pragma unroll
        for (int s = 0; s < 2; s++){
            uint32_t ah[2][4], al[2][4], bh[4][4], bl[4][4];
#pragma unroll
            for (int mt = 0; mt < 2; mt++)
                ldsm4(ah[mt], aTh + sw_off(aRow + mt*16, 2*s + aChk));
#pragma unroll
            for (int np = 0; np < 4; np++)
                ldsm4(bh[np], bTh + sw_off(bRow + np*16, 2*s + bChk));
#pragma unroll
            for (int mt = 0; mt < 2; mt++)
#pragma unroll
                for (int nt = 0; nt < 8; nt++){
                    const uint32_t* bb = bh[nt >> 1];
                    const int o = (nt & 1) * 2;
                    hmma(acc[mt][nt], ah[mt], bb[o], bb[o+1]);
                }
#pragma unroll
            for (int mt = 0; mt < 2; mt++)
                ldsm4(al[mt], aTl + sw_off(aRow + mt*16, 2*s + aChk));
#pragma unroll
            for (int mt = 0; mt < 2; mt++)
#pragma unroll
                for (int nt = 0; nt < 8; nt++){
                    const uint32_t* bb = bh[nt >> 1];
                    const int o = (nt & 1) * 2;
                    hmma(acc[mt][nt], al[mt], bb[o], bb[o+1]);
                }
#pragma unroll
            for (int np = 0; np < 4; np++)
                ldsm4(bl[np], bTl + sw_off(bRow + np*16, 2*s + bChk));
#pragma unroll
            for (int mt = 0; mt < 2; mt++)
#pragma unroll
                for (int nt = 0; nt < 8; nt++){
                    const uint32_t* bb = bl[nt >> 1];
                    const int o = (nt & 1) * 2;
                    hmma(acc[mt][nt], ah[mt], bb[o], bb[o+1]);
                }
        }
        if (kb + 2 < kbn){
            const int nidx = (stidx + 2 >= NSTAGE) ? stidx + 2 - NSTAGE : stidx + 2;
            load_stage4(sb + nidx*STAGE_B, pAh, pAl, pBh, pBl, lda, ldb, (kb+2)*BKh, tid);
        }
        stidx = (stidx + 1 == NSTAGE) ? 0 : stidx + 1;
    }

    // epilogue
    float invden = 1.0f;
    const float* knz = nullptr;
    if (MODE == E_LOGIT){
        invden = 1.0f / (fabsf(tau[0]) + 1e-6f);
        knz = knArr + (size_t)z * Sn;
    }
    const int rr = lane >> 2;
    const int cc = (lane & 3) * 2;
#pragma unroll
    for (int mt = 0; mt < 2; mt++){
#pragma unroll
        for (int nt = 0; nt < 8; nt++){
#pragma unroll
            for (int half = 0; half < 2; half++){
                int grow = mbase + wm*32 + mt*16 + rr + half*8;
                int gcol = nbase + wn*64 + nt*8 + cc;
                float v0 = acc[mt][nt][half*2 + 0];
                float v1 = acc[mt][nt][half*2 + 1];
                if (MODE == E_LOGIT){
                    v0 = (2.0f*v0 - knz[gcol])   * invden;
                    v1 = (2.0f*v1 - knz[gcol+1]) * invden;
                }
                if (MODE == E_SPLITPV){
                    bf16* dh = (nbase < HDn) ? OH : OH2;
                    bf16* dl = (nbase < HDn) ? OL : OL2;
                    size_t off = (size_t)grow*HIDn + (size_t)z*HDn + (gcol & (HDn-1));
                    uint32_t lo, hi = pack_hi(v0, v1, lo);
                    *(uint32_t*)(dh + off) = hi;
                    *(uint32_t*)(dl + off) = lo;
                } else {
                    float2 vv = make_float2(v0, v1);
                    float* dst = Cz + (size_t)grow*ldc + gcol;
                    *(float2*)dst = vv;
                }
            }
        }
    }
}

// ---------------- merged split: 10 matrices (8 W + xmu + xls), 8 elems/thread ---
__global__ void split10_v4(const float* __restrict__ w0, const float* __restrict__ w1,
                           const float* __restrict__ w2, const float* __restrict__ w3,
                           const float* __restrict__ w4, const float* __restrict__ w5,
                           const float* __restrict__ w6, const float* __restrict__ w7,
                           const float* __restrict__ xmu, const float* __restrict__ xls,
                           bf16* __restrict__ Wh, bf16* __restrict__ Wl,
                           bf16* __restrict__ Xmuh, bf16* __restrict__ Xmul,
                           bf16* __restrict__ Xlsh, bf16* __restrict__ Xlsl)
{
    const int w = blockIdx.y;
    const float* src;
    bf16 *dh, *dl;
    switch (w){
        case 0: src = w0;  dh = Wh + 0*(size_t)HIDn*HIDn; dl = Wl + 0*(size_t)HIDn*HIDn; break;
        case 1: src = w1;  dh = Wh + 1*(size_t)HIDn*HIDn; dl = Wl + 1*(size_t)HIDn*HIDn; break;
        case 2: src = w2;  dh = Wh + 2*(size_t)HIDn*HIDn; dl = Wl + 2*(size_t)HIDn*HIDn; break;
        case 3: src = w3;  dh = Wh + 3*(size_t)HIDn*HIDn; dl = Wl + 3*(size_t)HIDn*HIDn; break;
        case 4: src = w4;  dh = Wh + 4*(size_t)HIDn*HIDn; dl = Wl + 4*(size_t)HIDn*HIDn; break;
        case 5: src = w5;  dh = Wh + 5*(size_t)HIDn*HIDn; dl = Wl + 5*(size_t)HIDn*HIDn; break;
        case 6: src = w6;  dh = Wh + 6*(size_t)HIDn*HIDn; dl = Wl + 6*(size_t)HIDn*HIDn; break;
        case 7: src = w7;  dh = Wh + 7*(size_t)HIDn*HIDn; dl = Wl + 7*(size_t)HIDn*HIDn; break;
        case 8: src = xmu; dh = Xmuh; dl = Xmul; break;
        default: src = xls; dh = Xlsh; dl = Xlsl; break;
    }
    size_t i = (size_t)blockIdx.x*blockDim.x + threadIdx.x;
    const float4* in = (const float4*)src;
    float4 a = in[2*i], b = in[2*i + 1];
    float va[8] = {a.x, a.y, a.z, a.w, b.x, b.y, b.z, b.w};
    uint32_t hw[4], lw[4];
#pragma unroll
    for (int p = 0; p < 4; p++)
        hw[p] = pack_hi(va[2*p], va[2*p+1], lw[p]);
    ((uint4*)dh)[i] = make_uint4(hw[0], hw[1], hw[2], hw[3]);
    ((uint4*)dl)[i] = make_uint4(lw[0], lw[1], lw[2], lw[3]);
}

// ---------------- merged Q/K transform: rope + exp + split + kn(K only) ---------
__global__ void qk_transform2(const float* __restrict__ projBase,
                              const float* __restrict__ cosp, const float* __restrict__ sinp,
                              bf16* __restrict__ Qh, bf16* __restrict__ Ql,
                              bf16* __restrict__ Kh, bf16* __restrict__ Kl,
                              float* __restrict__ kn)
{
    const int which = blockIdx.z;
    const float* mu = projBase + (size_t)which     *Sn*HIDn;
    const float* ls = projBase + (size_t)(which+3) *Sn*HIDn;
    bf16* oh = which ? Kh : Qh;
    bf16* ol = which ? Kl : Ql;
    int s = blockIdx.x, h = blockIdx.y, d = threadIdx.x;
    size_t ib = (size_t)s*HIDn + h*HDn;
    float m = mu[ib + d];
    float o = mu[ib + ((d < 64) ? d + 64 : d - 64)];
    float c = cosp[s*HDn + d], sv = sinp[s*HDn + d];
    float roped = (d < 64) ? (m*c - o*sv) : (m*c + o*sv);
    float sg = expf(0.5f * ls[ib + d]);
    size_t ob = ((size_t)h*Sn + s)*DCn;
    bf16 hh = __float2bfloat16(roped);
    oh[ob + d] = hh; ol[ob + d] = __float2bfloat16(roped - __bfloat162float(hh));
    bf16 hs = __float2bfloat16(sg);
    oh[ob + 128 + d] = hs; ol[ob + 128 + d] = __float2bfloat16(sg - __bfloat162float(hs));
    if (which == 1){
        float acc = roped*roped + sg*sg;
#pragma unroll
        for (int off = 16; off; off >>= 1) acc += __shfl_xor_sync(0xffffffffu, acc, off);
        __shared__ float red[4];
        if ((d & 31) == 0) red[d>>5] = acc;
        __syncthreads();
        if (d == 0) kn[(size_t)h*Sn + s] = red[0] + red[1] + red[2] + red[3];
    }
}

// ---------------- V transpose + split via smem tiles (coalesced) ----------------
__global__ void v_transpose(const float* __restrict__ vmu, const float* __restrict__ vls,
                            bf16* __restrict__ oh, bf16* __restrict__ ol)
{
    __shared__ float t[32][33];
    const int h = blockIdx.z;
    const int dbase = blockIdx.y * 32;
    const int sbase = blockIdx.x * 32;
    const int tx = threadIdx.x, ty = threadIdx.y;
    const float* src = (dbase < HDn) ? vmu : vls;
    const int dcol = (dbase & (HDn-1)) + tx;
#pragma unroll
    for (int j = 0; j < 4; j++){
        int srow = sbase + ty + j*8;
        t[ty + j*8][tx] = src[(size_t)srow*HIDn + h*HDn + dcol];
    }
    __syncthreads();
#pragma unroll
    for (int j = 0; j < 4; j++){
        int d = dbase + ty + j*8;
        int s = sbase + tx;
        float v = t[tx][ty + j*8];
        size_t off = ((size_t)h*DCn + d)*Sn + s;
        bf16 hh = __float2bfloat16(v);
        oh[off] = hh;
        ol[off] = __float2bfloat16(v - __bfloat162float(hh));
    }
}

// ---------------- row softmax -> split bf16 hi/lo (vectorized loads AND stores) -
__global__ void softmax_split(const float* __restrict__ Pg, bf16* __restrict__ Ph,
                              bf16* __restrict__ Pl)
{
    const float4* p4 = (const float4*)(Pg + (size_t)blockIdx.x * Sn);
    uint2* ph2 = (uint2*)(Ph + (size_t)blockIdx.x * Sn);   // one uint2 = 2 bf162 = 4 elems
    uint2* pl2 = (uint2*)(Pl + (size_t)blockIdx.x * Sn);
    int tid = threadIdx.x;
    float4 x0 = p4[tid], x1 = p4[tid + 256];
    float v[8] = {x0.x, x0.y, x0.z, x0.w, x1.x, x1.y, x1.z, x1.w};
    float m = -1e30f;
#pragma unroll
    for (int i = 0; i < 8; i++) m = fmaxf(m, v[i]);
    __shared__ float redm[8], reds[8];
#pragma unroll
    for (int o = 16; o; o >>= 1) m = fmaxf(m, __shfl_xor_sync(0xffffffffu, m, o));
    if ((tid & 31) == 0) redm[tid>>5] = m;
    __syncthreads();
    if (tid < 32){
        float t = (tid < 8) ? redm[tid] : -1e30f;
#pragma unroll
        for (int o = 4; o; o >>= 1) t = fmaxf(t, __shfl_xor_sync(0xffffffffu, t, o));
        if (tid == 0) redm[0] = t;
    }
    __syncthreads();
    m = redm[0];
    float s = 0.f;
#pragma unroll
    for (int i = 0; i < 8; i++){ v[i] = __expf(v[i] - m); s += v[i]; }
#pragma unroll
    for (int o = 16; o; o >>= 1) s += __shfl_xor_sync(0xffffffffu, s, o);
    if ((tid & 31) == 0) reds[tid>>5] = s;
    __syncthreads();
    if (tid < 32){
        float t = (tid < 8) ? reds[tid] : 0.f;
#pragma unroll
        for (int o = 4; o; o >>= 1) t += __shfl_xor_sync(0xffffffffu, t, o);
        if (tid == 0) reds[0] = t;
    }
    __syncthreads();
    float inv = 1.f / reds[0];
    // elements held: v[0..3] = row[4t..4t+3], v[4..7] = row[1024+4t..1024+4t+3]
    // pack each group of 4 into one uint2 (2 bf162) -> fully coalesced 8B stores
#pragma unroll
    for (int c = 0; c < 2; c++){
        float p0 = v[c*4 + 0] * inv;
        float p1 = v[c*4 + 1] * inv;
        float p2 = v[c*4 + 2] * inv;
        float p3 = v[c*4 + 3] * inv;
        uint32_t lo0, hi0 = pack_hi(p0, p1, lo0);
        uint32_t lo1, hi1 = pack_hi(p2, p3, lo1);
        int idx = (c == 0) ? tid : 256 + tid;   // uint2 index: 4 elems per slot
        ph2[idx] = make_uint2(hi0, hi1);
        pl2[idx] = make_uint2(lo0, lo1);
    }
}

// ---------------- launch ----------------
extern "C" void kernel_launch(void* const* d_in, const int* in_sizes, int n_in,
                              void* d_out, int out_size)
{
    const float* xmu  = (const float*)d_in[0];
    const float* xls  = (const float*)d_in[1];
    const float* cosp = (const float*)d_in[2];
    const float* sinp = (const float*)d_in[3];
    const float* tau  = (const float*)d_in[12];
    float* out = (float*)d_out;

    bf16 *Xmu_h, *Xmu_l, *Xls_h, *Xls_l, *Wh, *Wl;
    bf16 *Qh, *Ql, *Kh, *Kl, *Vth, *Vtl, *Ph, *Pl;
    bf16 *Omh, *Oml, *Olh, *Oll;
    float *proj, *P, *kn;
    cudaGetSymbolAddress((void**)&Xmu_h, g_Xmu_h); cudaGetSymbolAddress((void**)&Xmu_l, g_Xmu_l);
    cudaGetSymbolAddress((void**)&Xls_h, g_Xls_h); cudaGetSymbolAddress((void**)&Xls_l, g_Xls_l);
    cudaGetSymbolAddress((void**)&Wh, g_W_h);      cudaGetSymbolAddress((void**)&Wl, g_W_l);
    cudaGetSymbolAddress((void**)&proj, g_proj);
    cudaGetSymbolAddress((void**)&Qh, g_Q_h);  cudaGetSymbolAddress((void**)&Ql, g_Q_l);
    cudaGetSymbolAddress((void**)&Kh, g_K_h);  cudaGetSymbolAddress((void**)&Kl, g_K_l);
    cudaGetSymbolAddress((void**)&Vth, g_Vt_h); cudaGetSymbolAddress((void**)&Vtl, g_Vt_l);
    cudaGetSymbolAddress((void**)&P, g_P);
    cudaGetSymbolAddress((void**)&Ph, g_P_h);  cudaGetSymbolAddress((void**)&Pl, g_P_l);
    cudaGetSymbolAddress((void**)&Omh, g_Om_h); cudaGetSymbolAddress((void**)&Oml, g_Om_l);
    cudaGetSymbolAddress((void**)&Olh, g_Ol_h); cudaGetSymbolAddress((void**)&Oll, g_Ol_l);
    cudaGetSymbolAddress((void**)&kn, g_kn);

    cudaFuncSetAttribute(hm_gemm<E_PROJ6>, cudaFuncAttributeMaxDynamicSharedMemorySize, SMEM_DYN);
    cudaFuncSetAttribute(hm_gemm<E_OUT2>,  cudaFuncAttributeMaxDynamicSharedMemorySize, SMEM_DYN);
    cudaFuncSetAttribute(hm_gemm<E_LOGIT>, cudaFuncAttributeMaxDynamicSharedMemorySize, SMEM_DYN);
    cudaFuncSetAttribute(hm_gemm<E_SPLITPV>,cudaFuncAttributeMaxDynamicSharedMemorySize, SMEM_DYN);

    const int NE = HIDn*HIDn;
    dim3 eb(256);

    split10_v4<<<dim3(NE/(256*8), 10), eb>>>(
        (const float*)d_in[4], (const float*)d_in[5], (const float*)d_in[6], (const float*)d_in[7],
        (const float*)d_in[8], (const float*)d_in[9], (const float*)d_in[10], (const float*)d_in[11],
        xmu, xls,
        Wh, Wl, Xmu_h, Xmu_l, Xls_h, Xls_l);

    dim3 blk(NTHR);
    size_t shm = SMEM_DYN;

    dim3 gp6(HIDn/BNh, Sn/BMh, 6);
    hm_gemm<E_PROJ6><<<gp6, blk, shm>>>(Xmu_h, Xmu_l, Xls_h, Xls_l, Wh, Wl,
        proj, nullptr,nullptr,nullptr,nullptr,
        HIDn, HIDn, HIDn, HIDn, 0,0,0, nullptr, nullptr);

    qk_transform2<<<dim3(Sn, NHn, 2), 128>>>(proj, cosp, sinp, Qh, Ql, Kh, Kl, kn);
    v_transpose<<<dim3(Sn/32, DCn/32, NHn), dim3(32,8)>>>(proj + 2*(size_t)Sn*HIDn, proj + 5*(size_t)Sn*HIDn, Vth, Vtl);

    dim3 gl(Sn/BNh, Sn/BMh, NHn);
    hm_gemm<E_LOGIT><<<gl, blk, shm>>>(Qh, Ql, nullptr, nullptr, Kh, Kl, P,
        nullptr,nullptr,nullptr,nullptr,
        DCn, DCn, DCn, Sn,
        (long long)Sn*DCn, (long long)Sn*DCn, (long long)Sn*Sn, kn, tau);

    softmax_split<<<NHn*Sn, 256>>>(P, Ph, Pl);

    dim3 gv(DCn/BNh, Sn/BMh, NHn);
    hm_gemm<E_SPLITPV><<<gv, blk, shm>>>(Ph, Pl, nullptr, nullptr, Vth, Vtl, nullptr,
        Omh, Oml, Olh, Oll,
        Sn, Sn, Sn, HIDn,
        (long long)Sn*Sn, (long long)DCn*Sn, 0, nullptr, nullptr);

    dim3 go2(HIDn/BNh, Sn/BMh, 2);
    hm_gemm<E_OUT2><<<go2, blk, shm>>>(Omh, Oml, Olh, Oll, Wh, Wl,
        out, nullptr,nullptr,nullptr,nullptr,
        HIDn, HIDn, HIDn, HIDn, 0,0,0, nullptr, nullptr);
}